// round 1
// baseline (speedup 1.0000x reference)
#include <cuda_runtime.h>
#include <cstdint>

#define NN 100000
#define EE 1600000
#define GG 1000
#define IN_C 32
#define EDGE_C 16
#define DESCC 200
#define HH 64
#define LL 3

// ---------------- device scratch (no allocs allowed) ----------------
__device__ float g_h[NN * HH];        // node hidden
__device__ float g_hp[NN * HH];       // h @ emW1_upper[l]  (message pre-projection)
__device__ float g_agg[NN * HH];      // segment-sum of relu(hidden)
__device__ float g_cnt[NN];           // in-degree (float)
__device__ float g_Wcomb[LL * EDGE_C * HH]; // edge_W @ emW1_lower[l]
__device__ float g_bcomb[LL * HH];          // edge_b @ emW1_lower[l] + emb1[l]
__device__ float g_pool[GG * HH];
__device__ float g_pcnt[GG];
__device__ int g_ei64;                // edge_index dtype flag (1 = int64)
__device__ int g_b64;                 // batch dtype flag

// ---------------- dtype detection ----------------
// If data is int32, interpreting tail elements as int64 combines two random
// in-range values -> huge number -> detect int32. If data is int64, values
// stay in range. Indices chosen so byte ranges are valid for BOTH dtypes.
__global__ void detect_kernel(const void* ei, const void* batch) {
    if (threadIdx.x == 0) {
        const long long* p = (const long long*)ei;
        int ok = 1;
        for (int i = 1; i <= 16; i++) {
            long long v = p[EE - i];   // valid for int32 buffer too (2E*4 = E*8 bytes)
            if (v < 0 || v >= NN) ok = 0;
        }
        g_ei64 = ok;
        const long long* q = (const long long*)batch;
        int okb = 1;
        for (int i = 1; i <= 16; i++) {
            long long v = q[NN / 2 - i]; // int32 view: tail elements (~G-1), int64 view: middle
            if (v < 0 || v >= GG) okb = 0;
        }
        g_b64 = okb;
    }
}

__device__ __forceinline__ long long load_idx(const void* p, long long i, int is64) {
    return is64 ? ((const long long*)p)[i] : (long long)((const int*)p)[i];
}

// ---------------- zero kernels ----------------
__global__ void zero_agg_kernel() {
    int i = blockIdx.x * blockDim.x + threadIdx.x;
    int stride = gridDim.x * blockDim.x;
    float4* p = (float4*)g_agg;
    const int n4 = NN * HH / 4;
    float4 z = make_float4(0.f, 0.f, 0.f, 0.f);
    for (; i < n4; i += stride) p[i] = z;
}

__global__ void zero_misc_kernel() {
    int i = blockIdx.x * blockDim.x + threadIdx.x;
    int stride = gridDim.x * blockDim.x;
    for (int k = i; k < NN; k += stride) g_cnt[k] = 0.f;
    for (int k = i; k < GG * HH; k += stride) g_pool[k] = 0.f;
    for (int k = i; k < GG; k += stride) g_pcnt[k] = 0.f;
}

// ---------------- in-degree ----------------
__global__ void count_kernel(const void* ei) {
    int is64 = g_ei64;
    int i = blockIdx.x * blockDim.x + threadIdx.x;
    int stride = gridDim.x * blockDim.x;
    for (; i < EE; i += stride) {
        long long dst = load_idx(ei, (long long)EE + i, is64);
        atomicAdd(&g_cnt[dst], 1.0f);
    }
}

// ---------------- composed edge weights: Wcomb[l] = edge_W @ emW1[l][64:128] ----------------
__global__ void wcomb_kernel(const float* edge_W, const float* edge_b,
                             const float* emW1, const float* emb1) {
    int t = threadIdx.x;             // 0..191
    int l = t >> 6, j = t & 63;
    const float* W1l = emW1 + l * (2 * HH * HH) + HH * HH; // rows 64..127
    for (int k = 0; k < EDGE_C; k++) {
        float acc = 0.f;
        for (int tt = 0; tt < HH; tt++) acc += edge_W[k * HH + tt] * W1l[tt * HH + j];
        g_Wcomb[l * EDGE_C * HH + k * HH + j] = acc;
    }
    float accb = emb1[l * HH + j];
    for (int tt = 0; tt < HH; tt++) accb += edge_b[tt] * W1l[tt * HH + j];
    g_bcomb[l * HH + j] = accb;
}

// ---------------- node init: h = x@node_W + b ; hp = h @ emW1[0][0:64] ----------------
__global__ void init_node_kernel(const float* __restrict__ x,
                                 const float* __restrict__ nW,
                                 const float* __restrict__ nb,
                                 const float* __restrict__ emW1) {
    __shared__ float sW[IN_C * HH];
    __shared__ float sP[HH * HH];
    __shared__ float sb[HH];
    __shared__ float sx[4][IN_C];
    __shared__ float sh[4][HH];
    int tid = threadIdx.x; // 256
    for (int i = tid; i < IN_C * HH; i += 256) sW[i] = nW[i];
    for (int i = tid; i < HH * HH; i += 256) sP[i] = emW1[i]; // layer0 upper rows
    if (tid < HH) sb[tid] = nb[tid];
    int tx = tid & 63, ty = tid >> 6;
    int node = blockIdx.x * 4 + ty;
    __syncthreads();
    if (node < NN && tx < IN_C) sx[ty][tx] = x[node * IN_C + tx];
    __syncthreads();
    float h = 0.f;
    if (node < NN) {
        h = sb[tx];
#pragma unroll
        for (int k = 0; k < IN_C; k++) h += sx[ty][k] * sW[k * HH + tx];
        g_h[node * HH + tx] = h;
        sh[ty][tx] = h;
    }
    __syncthreads();
    if (node < NN) {
        float hp = 0.f;
#pragma unroll 16
        for (int k = 0; k < HH; k++) hp += sh[ty][k] * sP[k * HH + tx];
        g_hp[node * HH + tx] = hp;
    }
}

// ---------------- edge kernel: hidden = relu(hp[src] + edge_attr@Wcomb + bcomb); agg[dst] += hidden
__global__ void edge_kernel(const void* __restrict__ ei,
                            const float* __restrict__ edge_attr, int l) {
    __shared__ float sW[EDGE_C * HH]; // 4 KB
    __shared__ float sb[HH];
    int tid = threadIdx.x;
    for (int i = tid; i < EDGE_C * HH; i += blockDim.x) sW[i] = g_Wcomb[l * EDGE_C * HH + i];
    if (tid < HH) sb[tid] = g_bcomb[l * HH + tid];
    __syncthreads();
    const int is64 = g_ei64;
    const int lane = tid & 31;
    const int q = tid & 15;                 // quad index (4 channels each)
    const int base16 = lane & 16;           // start lane of my 16-lane group
    const unsigned gmask = 0xFFFFu << base16;
    const long long* p64 = (const long long*)ei;
    const int* p32 = (const int*)ei;
    int e = blockIdx.x * (blockDim.x >> 4) + (tid >> 4);
    const int estride = gridDim.x * (blockDim.x >> 4);
    for (; e < EE; e += estride) {
        long long s64 = 0, d64 = 0;
        if (q == 0) {
            s64 = is64 ? p64[e] : (long long)p32[e];
            d64 = is64 ? p64[(long long)EE + e] : (long long)p32[EE + e];
        }
        s64 = __shfl_sync(gmask, s64, base16);
        d64 = __shfl_sync(gmask, d64, base16);
        int src = (int)s64, dst = (int)d64;
        float ea = edge_attr[(long long)e * EDGE_C + q];
        float4 acc = *(const float4*)(g_hp + (long long)src * HH + q * 4);
        float4 bb = *(const float4*)(sb + q * 4);
        acc.x += bb.x; acc.y += bb.y; acc.z += bb.z; acc.w += bb.w;
#pragma unroll
        for (int k = 0; k < EDGE_C; k++) {
            float a = __shfl_sync(gmask, ea, base16 + k);
            float4 w = *(const float4*)(sW + k * HH + q * 4);
            acc.x += a * w.x; acc.y += a * w.y; acc.z += a * w.z; acc.w += a * w.w;
        }
        acc.x = fmaxf(acc.x, 0.f); acc.y = fmaxf(acc.y, 0.f);
        acc.z = fmaxf(acc.z, 0.f); acc.w = fmaxf(acc.w, 0.f);
        float* dp = g_agg + (long long)dst * HH + q * 4;
        asm volatile("red.global.add.v4.f32 [%0], {%1,%2,%3,%4};"
                     :: "l"(dp), "f"(acc.x), "f"(acc.y), "f"(acc.z), "f"(acc.w)
                     : "memory");
    }
}

// ---------------- fused node update ----------------
// agg = aggH@emW2 + cnt*emb2 ; t = relu([h,agg]@umW1 + umb1) ;
// h' = t@umW2 + umb2 ; hp' = h' @ emW1[l+1][0:64]
#define NPT 16
#define NU_SMEM_FLOATS (4096 + 8192 + 4096 + 4096 + 3 * 64 + NPT * 64 + NPT * 128 + NPT * 64 + NPT)
__global__ void node_update_kernel(const float* __restrict__ emW2, const float* __restrict__ emb2,
                                   const float* __restrict__ umW1, const float* __restrict__ umb1,
                                   const float* __restrict__ umW2, const float* __restrict__ umb2,
                                   const float* __restrict__ emW1, int l, int has_next) {
    extern __shared__ float sm[];
    float* sW2 = sm;                // emW2   [64x64]
    float* sU1 = sW2 + 4096;        // umW1   [128x64]
    float* sU2 = sU1 + 8192;        // umW2   [64x64]
    float* sP  = sU2 + 4096;        // emW1 upper next layer [64x64]
    float* sb2 = sP + 4096;
    float* sub1 = sb2 + 64;
    float* sub2 = sub1 + 64;
    float* sA = sub2 + 64;          // [NPT][64] agg rows, later reused for h'
    float* sU = sA + NPT * 64;      // [NPT][128] concat(h, agg)
    float* sT = sU + NPT * 128;     // [NPT][64]
    float* sC = sT + NPT * 64;      // [NPT] counts
    int tid = threadIdx.x;          // 256
    const float* w2 = emW2 + l * 4096;
    const float* u1 = umW1 + l * 8192;
    const float* u2 = umW2 + l * 4096;
    const float* pn = emW1 + (l + 1) * 8192;
    for (int i = tid; i < 4096; i += 256) {
        sW2[i] = w2[i]; sU2[i] = u2[i]; sP[i] = has_next ? pn[i] : 0.f;
    }
    for (int i = tid; i < 8192; i += 256) sU1[i] = u1[i];
    if (tid < 64) { sb2[tid] = emb2[l * 64 + tid]; sub1[tid] = umb1[l * 64 + tid]; sub2[tid] = umb2[l * 64 + tid]; }
    __syncthreads();
    int tx = tid & 63, g = tid >> 6;
    int n0 = g * 4, n1 = g * 4 + 1, n2 = g * 4 + 2, n3 = g * 4 + 3;
    for (int nb = blockIdx.x * NPT; nb < NN; nb += gridDim.x * NPT) {
        // stage in agg + h rows
#pragma unroll
        for (int r = 0; r < NPT * 64 / 256; r++) {
            int idx = tid + r * 256;
            int nloc = idx >> 6, ch = idx & 63;
            int node = nb + nloc;
            float a = 0.f, hv = 0.f;
            if (node < NN) { a = g_agg[(long long)node * 64 + ch]; hv = g_h[(long long)node * 64 + ch]; }
            sA[nloc * 64 + ch] = a;
            sU[nloc * 128 + ch] = hv;
        }
        if (tid < NPT) { int node = nb + tid; sC[tid] = node < NN ? g_cnt[node] : 0.f; }
        __syncthreads();
        // stage 1: agg projection -> sU[:,64:128]
        {
            float a0 = sC[n0] * sb2[tx], a1 = sC[n1] * sb2[tx], a2 = sC[n2] * sb2[tx], a3 = sC[n3] * sb2[tx];
#pragma unroll 16
            for (int k = 0; k < 64; k++) {
                float w = sW2[k * 64 + tx];
                a0 += sA[n0 * 64 + k] * w; a1 += sA[n1 * 64 + k] * w;
                a2 += sA[n2 * 64 + k] * w; a3 += sA[n3 * 64 + k] * w;
            }
            sU[n0 * 128 + 64 + tx] = a0; sU[n1 * 128 + 64 + tx] = a1;
            sU[n2 * 128 + 64 + tx] = a2; sU[n3 * 128 + 64 + tx] = a3;
        }
        __syncthreads();
        // stage 2: t = relu(u @ umW1 + b)
        {
            float a0 = sub1[tx], a1 = a0, a2 = a0, a3 = a0;
#pragma unroll 16
            for (int k = 0; k < 128; k++) {
                float w = sU1[k * 64 + tx];
                a0 += sU[n0 * 128 + k] * w; a1 += sU[n1 * 128 + k] * w;
                a2 += sU[n2 * 128 + k] * w; a3 += sU[n3 * 128 + k] * w;
            }
            sT[n0 * 64 + tx] = fmaxf(a0, 0.f); sT[n1 * 64 + tx] = fmaxf(a1, 0.f);
            sT[n2 * 64 + tx] = fmaxf(a2, 0.f); sT[n3 * 64 + tx] = fmaxf(a3, 0.f);
        }
        __syncthreads();
        // stage 3: h' = t @ umW2 + b  (write g_h, stash into sA for stage 4)
        {
            float a0 = sub2[tx], a1 = a0, a2 = a0, a3 = a0;
#pragma unroll 16
            for (int k = 0; k < 64; k++) {
                float w = sU2[k * 64 + tx];
                a0 += sT[n0 * 64 + k] * w; a1 += sT[n1 * 64 + k] * w;
                a2 += sT[n2 * 64 + k] * w; a3 += sT[n3 * 64 + k] * w;
            }
            if (nb + n0 < NN) g_h[(long long)(nb + n0) * 64 + tx] = a0;
            if (nb + n1 < NN) g_h[(long long)(nb + n1) * 64 + tx] = a1;
            if (nb + n2 < NN) g_h[(long long)(nb + n2) * 64 + tx] = a2;
            if (nb + n3 < NN) g_h[(long long)(nb + n3) * 64 + tx] = a3;
            __syncthreads();
            sA[n0 * 64 + tx] = a0; sA[n1 * 64 + tx] = a1;
            sA[n2 * 64 + tx] = a2; sA[n3 * 64 + tx] = a3;
        }
        __syncthreads();
        // stage 4: hp' = h' @ emW1[l+1] upper
        if (has_next) {
            float a0 = 0.f, a1 = 0.f, a2 = 0.f, a3 = 0.f;
#pragma unroll 16
            for (int k = 0; k < 64; k++) {
                float w = sP[k * 64 + tx];
                a0 += sA[n0 * 64 + k] * w; a1 += sA[n1 * 64 + k] * w;
                a2 += sA[n2 * 64 + k] * w; a3 += sA[n3 * 64 + k] * w;
            }
            if (nb + n0 < NN) g_hp[(long long)(nb + n0) * 64 + tx] = a0;
            if (nb + n1 < NN) g_hp[(long long)(nb + n1) * 64 + tx] = a1;
            if (nb + n2 < NN) g_hp[(long long)(nb + n2) * 64 + tx] = a2;
            if (nb + n3 < NN) g_hp[(long long)(nb + n3) * 64 + tx] = a3;
        }
        __syncthreads();
    }
}

// ---------------- global mean pool (sum + count) ----------------
__global__ void pool_kernel(const void* __restrict__ batch) {
    int is64 = g_b64;
    long long i = (long long)blockIdx.x * blockDim.x + threadIdx.x;
    if (i >= (long long)NN * 64) return;
    long long node = i >> 6; int ch = (int)(i & 63);
    long long b = load_idx(batch, node, is64);
    atomicAdd(&g_pool[b * 64 + ch], g_h[i]);
    if (ch == 0) atomicAdd(&g_pcnt[b], 1.0f);
}

// ---------------- readout: sigmoid(relu([pooled,desc]@W1+b1)@W2+b2) ----------------
__global__ void readout_kernel(const float* __restrict__ desc,
                               const float* __restrict__ W1, const float* __restrict__ b1,
                               const float* __restrict__ W2, const float* __restrict__ b2,
                               float* __restrict__ out) {
    __shared__ float r[HH + DESCC];
    __shared__ float st[128];
    int g = blockIdx.x, tid = threadIdx.x; // 128 threads
    float cn = fmaxf(g_pcnt[g], 1.0f);
    for (int i = tid; i < HH; i += 128) r[i] = g_pool[g * HH + i] / cn;
    for (int i = tid; i < DESCC; i += 128) r[HH + i] = desc[(long long)g * DESCC + i];
    __syncthreads();
    float acc = b1[tid];
#pragma unroll 8
    for (int k = 0; k < HH + DESCC; k++) acc += r[k] * W1[k * 128 + tid];
    acc = fmaxf(acc, 0.f);
    st[tid] = acc * W2[tid];
    __syncthreads();
    for (int s = 64; s > 0; s >>= 1) {
        if (tid < s) st[tid] += st[tid + s];
        __syncthreads();
    }
    if (tid == 0) out[g] = 1.0f / (1.0f + expf(-(st[0] + b2[0])));
}

// ---------------- launch ----------------
extern "C" void kernel_launch(void* const* d_in, const int* in_sizes, int n_in,
                              void* d_out, int out_size) {
    const float* x       = (const float*)d_in[0];
    const void*  ei      = d_in[1];
    const float* eattr   = (const float*)d_in[2];
    const void*  batch   = d_in[3];
    const float* desc    = (const float*)d_in[4];
    const float* node_W  = (const float*)d_in[5];
    const float* node_b  = (const float*)d_in[6];
    const float* edge_W  = (const float*)d_in[7];
    const float* edge_b  = (const float*)d_in[8];
    const float* emW1    = (const float*)d_in[9];
    const float* emb1    = (const float*)d_in[10];
    const float* emW2    = (const float*)d_in[11];
    const float* emb2    = (const float*)d_in[12];
    const float* umW1    = (const float*)d_in[13];
    const float* umb1    = (const float*)d_in[14];
    const float* umW2    = (const float*)d_in[15];
    const float* umb2    = (const float*)d_in[16];
    const float* roW1    = (const float*)d_in[17];
    const float* rob1    = (const float*)d_in[18];
    const float* roW2    = (const float*)d_in[19];
    const float* rob2    = (const float*)d_in[20];
    float* out = (float*)d_out;

    const int nu_smem = NU_SMEM_FLOATS * (int)sizeof(float);
    cudaFuncSetAttribute(node_update_kernel,
                         cudaFuncAttributeMaxDynamicSharedMemorySize, nu_smem);

    detect_kernel<<<1, 32>>>(ei, batch);
    zero_misc_kernel<<<1024, 256>>>();
    count_kernel<<<2048, 256>>>(ei);
    wcomb_kernel<<<1, 192>>>(edge_W, edge_b, emW1, emb1);
    init_node_kernel<<<(NN + 3) / 4, 256>>>(x, node_W, node_b, emW1);
    for (int l = 0; l < LL; l++) {
        zero_agg_kernel<<<2048, 256>>>();
        edge_kernel<<<4096, 256>>>(ei, eattr, l);
        node_update_kernel<<<296, 256, nu_smem>>>(emW2, emb2, umW1, umb1,
                                                  umW2, umb2, emW1, l, l < LL - 1 ? 1 : 0);
    }
    pool_kernel<<<(NN * 64 + 255) / 256, 256>>>(batch);
    readout_kernel<<<GG, 128>>>(desc, roW1, rob1, roW2, rob2, out);
}